// round 6
// baseline (speedup 1.0000x reference)
#include <cuda_runtime.h>
#include <cuda_bf16.h>

#define HH 28
#define WW 28
#define KK 7
#define NTAP 49
#define BATCH 512
#define NBR 8
#define FEAT 392

#define IMG_PER_BLK 4
#define STRIPS 56                         // 28 rows x 2 col-strips of 14
#define THREADS_A (IMG_PER_BLK * STRIPS)  // 224

#define VROWS 34                 // 28 + 2*3 halo
#define VW 36                    // padded row stride (floats, even for float2)
#define VPLANE (VROWS * VW)      // 1224 floats per plane

typedef unsigned long long u64;
union F2U { float2 f; u64 u; };

__device__ float g_feat[BATCH * FEAT];
// float4-packed transposed weights (R4 layout, verified rel_err 7.4e-8)
__device__ float4 g_w1p[98 * 120];
__device__ float4 g_w2p[30 * 84];
__device__ float4 g_w3p[21 * 10];
#define N_W1P (98 * 120)
#define N_W2P (30 * 84)
#define N_W3P (21 * 10)

#define FMA2(acc, a, b) asm("fma.rn.f32x2 %0, %1, %2, %0;" : "+l"(acc) : "l"(a), "l"(b))
#define ADD2(d, a, b)   asm("add.rn.f32x2 %0, %1, %2;" : "=l"(d) : "l"(a), "l"(b))
#define PACK2(d, lo, hi) asm("mov.b64 %0, {%1, %2};" : "=l"(d) : "f"(lo), "f"(hi))
#define UNPK2(lo, hi, s) asm("mov.b64 {%0, %1}, %2;" : "=f"(lo), "=f"(hi) : "l"(s))

// SMorph factorization:  out = (sum c1*u + sum c2*v) / (sum c1*v)
// v = exp(a*x), u = x*v, c1 = exp(a*w), c2 = w*c1.  Zero SAME-pad <=> (v,u)=(1,0).
// Split v/u planes; thread owns a 14x1 strip; all three sums run as f32x2
// FMAs over pixel pairs (1.5 FMA-inst per tap-pixel).
__global__ void __launch_bounds__(THREADS_A)
smorph_branch_kernel(const float* __restrict__ x,
                     const float* __restrict__ sm_w,      // [8,2,7,7]
                     const float* __restrict__ sm_alpha,  // [8,2]
                     const float* __restrict__ W1,
                     const float* __restrict__ W2,
                     const float* __restrict__ W3)
{
    extern __shared__ float smem[];
    float* vbase = smem;                         // [4][VPLANE] v
    float* ubase = smem + 4 * VPLANE;            // [4][VPLANE] u (reused as sy)
    float* scp2  = ubase + 4 * VPLANE;           // [49] float2 (c1,c1)
    float* sc2p  = scp2 + 2 * NTAP;              // [49] float2 (c2,c2)

    const int tid = threadIdx.x;
    const int b0  = blockIdx.x * IMG_PER_BLK;
    const int r   = blockIdx.y;

    // ---- folded one-shot weight repack (R4-identical) ----
    {
        int gid = blockIdx.y * gridDim.x + blockIdx.x;
        int t = gid * THREADS_A + tid;
        if (t < N_W1P) {
            int i4 = t / 120, j = t % 120;
            g_w1p[t] = *(const float4*)(W1 + j * FEAT + 4 * i4);
        } else if (t < N_W1P + N_W2P) {
            int q = t - N_W1P; int i4 = q / 84, j = q % 84;
            g_w2p[q] = *(const float4*)(W2 + j * 120 + 4 * i4);
        } else if (t < N_W1P + N_W2P + N_W3P) {
            int q = t - N_W1P - N_W2P; int i4 = q / 10, j = q % 10;
            g_w3p[q] = *(const float4*)(W3 + j * 84 + 4 * i4);
        }
    }

    const int img = tid / STRIPS;
    const int s   = tid % STRIPS;
    const int pr  = s >> 1;           // output row 0..27
    const int pcs = (s & 1) * 14;     // strip col base: 0 or 14

    float* vpl = vbase + img * VPLANE;
    float* upl = ubase + img * VPLANE;
    const float* xim = x + (b0 + img) * (HH * WW);

    const float a0 = sm_alpha[r * 2 + 0];
    const float a1 = sm_alpha[r * 2 + 1];

    // halo init (v,u) = (1,0) everywhere
    for (int i = tid; i < IMG_PER_BLK * VPLANE; i += THREADS_A) {
        vbase[i] = 1.0f; ubase[i] = 0.0f;
    }
    // layer-0 coefficients
    if (tid < NTAP) {
        float wv = sm_w[(r * 2 + 0) * NTAP + tid];
        float c1 = __expf(a0 * wv);
        scp2[2 * tid] = c1; scp2[2 * tid + 1] = c1;
        float c2 = c1 * wv;
        sc2p[2 * tid] = c2; sc2p[2 * tid + 1] = c2;
    }
    __syncthreads();

    // layer-0 interior fill (thread fills its own 14-px row segment)
    {
        const float2* xr2 = (const float2*)(xim + pr * WW + pcs);
        #pragma unroll
        for (int k = 0; k < 7; k++) {
            float2 xp = xr2[k];
            int off = (pr + 3) * VW + 3 + pcs + 2 * k;
            float v0 = __expf(a0 * xp.x);
            float v1 = __expf(a0 * xp.y);
            vpl[off] = v0;     vpl[off + 1] = v1;
            upl[off] = xp.x * v0; upl[off + 1] = xp.y * v1;
        }
    }
    __syncthreads();

    const float2* vp2 = (const float2*)vpl;
    const float2* up2 = (const float2*)upl;
    const u64* cp64  = (const u64*)scp2;
    const u64* c2p64 = (const u64*)sc2p;

    float y[14];

    #pragma unroll 1
    for (int L = 0; L < 2; L++) {
        u64 accD[7], accU[7], accW[7];
        #pragma unroll
        for (int m = 0; m < 7; m++) { accD[m] = 0ull; accU[m] = 0ull; accW[m] = 0ull; }

        #pragma unroll
        for (int dy = 0; dy < 7; dy++) {
            F2U ve[10], ue[10];
            const int rb = (pr + dy) * (VW / 2) + (pcs >> 1);
            #pragma unroll
            for (int k = 0; k < 10; k++) { ve[k].f = vp2[rb + k]; ue[k].f = up2[rb + k]; }
            u64 vo[9], uo[9];
            #pragma unroll
            for (int k = 0; k < 9; k++) {
                PACK2(vo[k], ve[k].f.y, ve[k + 1].f.x);
                PACK2(uo[k], ue[k].f.y, ue[k + 1].f.x);
            }
            #pragma unroll
            for (int dx = 0; dx < 7; dx++) {
                const u64 c1p = cp64[dy * 7 + dx];
                const u64 c2p = c2p64[dy * 7 + dx];
                #pragma unroll
                for (int m = 0; m < 7; m++) {
                    u64 vv, uu;
                    if ((dx & 1) == 0) { vv = ve[m + (dx >> 1)].u; uu = ue[m + (dx >> 1)].u; }
                    else               { vv = vo[m + ((dx - 1) >> 1)]; uu = uo[m + ((dx - 1) >> 1)]; }
                    FMA2(accD[m], c1p, vv);
                    FMA2(accU[m], c1p, uu);
                    FMA2(accW[m], c2p, vv);
                }
            }
        }

        #pragma unroll
        for (int m = 0; m < 7; m++) {
            u64 nsum; ADD2(nsum, accU[m], accW[m]);
            float n0, n1, d0, d1;
            UNPK2(n0, n1, nsum);
            UNPK2(d0, d1, accD[m]);
            y[2 * m]     = __fdividef(n0, d0);
            y[2 * m + 1] = __fdividef(n1, d1);
        }
        __syncthreads();   // all conv reads of planes & coeffs done

        if (L == 0) {
            if (tid < NTAP) {
                float wv = sm_w[(r * 2 + 1) * NTAP + tid];
                float c1 = __expf(a1 * wv);
                scp2[2 * tid] = c1; scp2[2 * tid + 1] = c1;
                float c2 = c1 * wv;
                sc2p[2 * tid] = c2; sc2p[2 * tid + 1] = c2;
            }
            #pragma unroll
            for (int c = 0; c < 14; c++) {
                float yi = y[c];
                float vv = __expf(a1 * yi);
                int off = (pr + 3) * VW + 3 + pcs + c;
                vpl[off] = vv;
                upl[off] = yi * vv;
            }
        } else {
            // final layer output -> scalar sy overlaid on this image's u-plane
            #pragma unroll
            for (int c = 0; c < 14; c++)
                upl[pr * WW + pcs + c] = y[c];
        }
        __syncthreads();
    }

    // ---- 4x4 avg pool -> [7,7] features ----
    if (s < NTAP) {
        int qr = s / 7, qc = s % 7;
        float acc = 0.0f;
        #pragma unroll
        for (int dy = 0; dy < 4; dy++)
            #pragma unroll
            for (int dx = 0; dx < 4; dx++)
                acc += upl[(qr * 4 + dy) * WW + qc * 4 + dx];
        g_feat[(b0 + img) * FEAT + r * NTAP + s] = acc * (1.0f / 16.0f);
    }
}

__device__ __forceinline__ float sigf(float z) {
    return 1.0f / (1.0f + __expf(-z));
}

// Fused 3-layer sigmoid MLP: arithmetic bit-identical to Round 4
// (rel_err 7.4e-8), but weights cooperatively staged through shared memory
// in chunks so per-thread loads are LDS instead of latency-exposed LDG.
#define MROWS 4
__global__ void __launch_bounds__(128) mlp_kernel(
    const float* __restrict__ b1,
    const float* __restrict__ b2,
    const float* __restrict__ b3,
    float* __restrict__ out)
{
    __shared__ float sf [MROWS][FEAT];
    __shared__ float sh1[MROWS][120];
    __shared__ float sh2[MROWS][84];
    __shared__ float4 swb[1800];          // staging buffer (28.8KB)

    const int tid = threadIdx.x;
    const int b0  = blockIdx.x * MROWS;

    {
        const float4* src = (const float4*)(g_feat + b0 * FEAT);
        float4* dst = (float4*)sf;
        for (int i = tid; i < MROWS * FEAT / 4; i += 128) dst[i] = src[i];
    }
    __syncthreads();

    // ---- 392 -> 120 : 7 chunks of 14 i4-groups ----
    float acc0 = 0.f, acc1 = 0.f, acc2 = 0.f, acc3 = 0.f;
    if (tid < 120) { float bb = b1[tid]; acc0 = bb; acc1 = bb; acc2 = bb; acc3 = bb; }
    #pragma unroll 1
    for (int c = 0; c < 7; c++) {
        for (int i = tid; i < 14 * 120; i += 128) swb[i] = g_w1p[c * (14 * 120) + i];
        __syncthreads();
        if (tid < 120) {
            #pragma unroll
            for (int i4 = 0; i4 < 14; i4++) {
                float4 w  = swb[i4 * 120 + tid];
                const int g = (c * 14 + i4) * 4;
                float4 s0 = *(const float4*)&sf[0][g];
                float4 s1 = *(const float4*)&sf[1][g];
                float4 s2 = *(const float4*)&sf[2][g];
                float4 s3 = *(const float4*)&sf[3][g];
                acc0 = fmaf(w.x, s0.x, fmaf(w.y, s0.y, fmaf(w.z, s0.z, fmaf(w.w, s0.w, acc0))));
                acc1 = fmaf(w.x, s1.x, fmaf(w.y, s1.y, fmaf(w.z, s1.z, fmaf(w.w, s1.w, acc1))));
                acc2 = fmaf(w.x, s2.x, fmaf(w.y, s2.y, fmaf(w.z, s2.z, fmaf(w.w, s2.w, acc2))));
                acc3 = fmaf(w.x, s3.x, fmaf(w.y, s3.y, fmaf(w.z, s3.z, fmaf(w.w, s3.w, acc3))));
            }
        }
        __syncthreads();
    }
    if (tid < 120) {
        sh1[0][tid] = sigf(acc0);
        sh1[1][tid] = sigf(acc1);
        sh1[2][tid] = sigf(acc2);
        sh1[3][tid] = sigf(acc3);
    }
    __syncthreads();

    // ---- 120 -> 84 : 2 chunks of 15 i4-groups ----
    acc0 = acc1 = acc2 = acc3 = 0.f;
    if (tid < 84) { float bb = b2[tid]; acc0 = bb; acc1 = bb; acc2 = bb; acc3 = bb; }
    #pragma unroll 1
    for (int c = 0; c < 2; c++) {
        for (int i = tid; i < 15 * 84; i += 128) swb[i] = g_w2p[c * (15 * 84) + i];
        __syncthreads();
        if (tid < 84) {
            #pragma unroll
            for (int i4 = 0; i4 < 15; i4++) {
                float4 w  = swb[i4 * 84 + tid];
                const int g = (c * 15 + i4) * 4;
                float4 s0 = *(const float4*)&sh1[0][g];
                float4 s1 = *(const float4*)&sh1[1][g];
                float4 s2 = *(const float4*)&sh1[2][g];
                float4 s3 = *(const float4*)&sh1[3][g];
                acc0 = fmaf(w.x, s0.x, fmaf(w.y, s0.y, fmaf(w.z, s0.z, fmaf(w.w, s0.w, acc0))));
                acc1 = fmaf(w.x, s1.x, fmaf(w.y, s1.y, fmaf(w.z, s1.z, fmaf(w.w, s1.w, acc1))));
                acc2 = fmaf(w.x, s2.x, fmaf(w.y, s2.y, fmaf(w.z, s2.z, fmaf(w.w, s2.w, acc2))));
                acc3 = fmaf(w.x, s3.x, fmaf(w.y, s3.y, fmaf(w.z, s3.z, fmaf(w.w, s3.w, acc3))));
            }
        }
        __syncthreads();
    }
    if (tid < 84) {
        sh2[0][tid] = sigf(acc0);
        sh2[1][tid] = sigf(acc1);
        sh2[2][tid] = sigf(acc2);
        sh2[3][tid] = sigf(acc3);
    }
    __syncthreads();

    // ---- 84 -> 10 ----
    for (int i = tid; i < N_W3P; i += 128) swb[i] = g_w3p[i];
    __syncthreads();
    if (tid < 40) {
        const int j  = tid % 10;
        const int rr = tid / 10;
        float acc = b3[j];
        #pragma unroll
        for (int i4 = 0; i4 < 21; i4++) {
            float4 w = swb[i4 * 10 + j];
            float4 s = *(const float4*)&sh2[rr][i4 * 4];
            acc = fmaf(w.x, s.x, fmaf(w.y, s.y, fmaf(w.z, s.z, fmaf(w.w, s.w, acc))));
        }
        out[(b0 + rr) * 10 + j] = sigf(acc);
    }
}

extern "C" void kernel_launch(void* const* d_in, const int* in_sizes, int n_in,
                              void* d_out, int out_size)
{
    const float* x        = (const float*)d_in[0];
    const float* sm_w     = (const float*)d_in[1];
    const float* sm_alpha = (const float*)d_in[2];
    const float* W1       = (const float*)d_in[3];
    const float* b1       = (const float*)d_in[4];
    const float* W2       = (const float*)d_in[5];
    const float* b2       = (const float*)d_in[6];
    const float* W3       = (const float*)d_in[7];
    const float* b3       = (const float*)d_in[8];
    float* out = (float*)d_out;

    const int smem_bytes =
        (8 * VPLANE + 4 * NTAP) * (int)sizeof(float);   // ~39.9KB

    dim3 gridA(BATCH / IMG_PER_BLK, NBR);   // (128, 8)
    smorph_branch_kernel<<<gridA, THREADS_A, smem_bytes>>>(
        x, sm_w, sm_alpha, W1, W2, W3);

    mlp_kernel<<<BATCH / MROWS, 128>>>(b1, b2, b3, out);
}

// round 7
// speedup vs baseline: 1.0294x; 1.0294x over previous
#include <cuda_runtime.h>
#include <cuda_bf16.h>

#define HH 28
#define WW 28
#define PAD 3
#define PW 35           // padded width (odd -> spread smem banks)
#define KK 7
#define NTAP 49
#define BATCH 512
#define NBR 8
#define FEAT 392        // 8 branches * 49

#define IMG_PER_BLK 4
#define STRIPS 56       // (28/7 cols) x (28/2 rows) strips per image
#define THREADS_A (IMG_PER_BLK * STRIPS)   // 224 = 7 full warps

typedef unsigned long long u64;
union F2U { float2 f; u64 u; };

__device__ float g_feat[BATCH * FEAT];
// float4-packed transposed weights: 4 consecutive K-steps per element.
__device__ float4 g_w1p[98 * 120];   // [i4][j]  w = W1[j][4*i4 .. 4*i4+3]
__device__ float4 g_w2p[30 * 84];    // [i4][j]
__device__ float4 g_w3p[21 * 10];    // [i4][j]
#define N_W1P (98 * 120)
#define N_W2P (30 * 84)
#define N_W3P (21 * 10)

#define FMA2(acc, a, b) asm("fma.rn.f32x2 %0, %1, %2, %0;" : "+l"(acc) : "l"(a), "l"(b))

// SMorph factorization:  out = (sum c1*u + sum c2*v) / (sum c1*v)
// v = exp(a*x), u = x*v, c1 = exp(a*w), c2 = w*c1.  Zero SAME-pad <=> (v,u)=(1,0).
// One block = 4 images x 1 branch; each thread owns a 7x2 output strip.
// (Round-4 version, verbatim: measured ~40.4us, rel_err 7.4e-8.)
__global__ void __launch_bounds__(THREADS_A)
smorph_branch_kernel(const float* __restrict__ x,
                     const float* __restrict__ sm_w,      // [8,2,7,7]
                     const float* __restrict__ sm_alpha,  // [8,2]
                     const float* __restrict__ W1,        // for folded repack
                     const float* __restrict__ W2,
                     const float* __restrict__ W3)
{
    extern __shared__ float smem[];
    float* svu = smem;                              // [4][PW*PW][2]
    float* scp = svu + IMG_PER_BLK * PW * PW * 2;   // [49] float2 (c1,c1)
    float* sc2 = scp + 2 * NTAP;                    // [49]

    const int tid = threadIdx.x;
    const int b0  = blockIdx.x * IMG_PER_BLK;
    const int r   = blockIdx.y;

    // ---- folded one-shot weight repack (float4 of 4 consecutive K-steps) ----
    {
        int gid = blockIdx.y * gridDim.x + blockIdx.x;
        int t = gid * THREADS_A + tid;
        if (t < N_W1P) {
            int i4 = t / 120, j = t % 120;
            g_w1p[t] = *(const float4*)(W1 + j * FEAT + 4 * i4);
        } else if (t < N_W1P + N_W2P) {
            int q = t - N_W1P; int i4 = q / 84, j = q % 84;
            g_w2p[q] = *(const float4*)(W2 + j * 120 + 4 * i4);
        } else if (t < N_W1P + N_W2P + N_W3P) {
            int q = t - N_W1P - N_W2P; int i4 = q / 10, j = q % 10;
            g_w3p[q] = *(const float4*)(W3 + j * 84 + 4 * i4);
        }
    }

    const int img = tid / STRIPS;
    const int s   = tid % STRIPS;
    const int pr0 = (s / 4) * 2;   // strip top row   (0..26)
    const int pc0 = (s % 4) * 7;   // strip left col  (0,7,14,21)

    float2* myvu = (float2*)svu + img * (PW * PW);
    const float* xim = x + (b0 + img) * (HH * WW);

    const float a0 = sm_alpha[r * 2 + 0];
    const float a1 = sm_alpha[r * 2 + 1];

    // init to halo (v,u)=(1,0); interior overwritten below
    {
        float2* p = (float2*)svu;
        for (int i = tid; i < IMG_PER_BLK * PW * PW; i += THREADS_A)
            p[i] = make_float2(1.0f, 0.0f);
    }
    // layer-0 coefficients
    if (tid < NTAP) {
        float wv = sm_w[(r * 2 + 0) * NTAP + tid];
        float c1 = __expf(a0 * wv);
        scp[2 * tid] = c1; scp[2 * tid + 1] = c1;
        sc2[tid] = c1 * wv;
    }
    __syncthreads();

    // layer-0 interior fill
    for (int i = s; i < HH * WW; i += STRIPS) {
        float xi = xim[i];
        float vv = __expf(a0 * xi);
        int pr = i / WW, pc = i % WW;
        myvu[(pr + PAD) * PW + pc + PAD] = make_float2(vv, xi * vv);
    }
    __syncthreads();

    float y[2][7];

    #pragma unroll 1
    for (int L = 0; L < 2; L++) {
        // ---- conv: 7x2 strip, 8 input rows, coefficient rows cached in regs ----
        u64   acc2[2][7];    // packed (den = sum c1*v, num_u = sum c1*u)
        float accw[2][7];    // sum c2*v
        #pragma unroll
        for (int i = 0; i < 2; i++)
            #pragma unroll
            for (int j = 0; j < 7; j++) { acc2[i][j] = 0ull; accw[i][j] = 0.0f; }

        F2U cc_cur[7], cc_prev[7];
        float c2_cur[7], c2_prev[7];

        #pragma unroll
        for (int dy = 0; dy < 8; dy++) {
            F2U t[13];
            const float2* rowp = myvu + (pr0 + dy) * PW + pc0;
            #pragma unroll
            for (int k = 0; k < 13; k++) t[k].f = rowp[k];

            if (dy < 7) {
                #pragma unroll
                for (int dx = 0; dx < 7; dx++) {
                    cc_cur[dx].f = ((const float2*)scp)[dy * 7 + dx];
                    c2_cur[dx]   = sc2[dy * 7 + dx];
                }
                // sr = 0 uses tap row ky = dy
                #pragma unroll
                for (int dx = 0; dx < 7; dx++) {
                    u64 c = cc_cur[dx].u; float c2 = c2_cur[dx];
                    #pragma unroll
                    for (int scx = 0; scx < 7; scx++) {
                        FMA2(acc2[0][scx], c, t[dx + scx].u);
                        accw[0][scx] = fmaf(c2, t[dx + scx].f.x, accw[0][scx]);
                    }
                }
            }
            if (dy >= 1) {
                // sr = 1 uses tap row ky = dy-1 (cached from previous iteration)
                #pragma unroll
                for (int dx = 0; dx < 7; dx++) {
                    u64 c = cc_prev[dx].u; float c2 = c2_prev[dx];
                    #pragma unroll
                    for (int scx = 0; scx < 7; scx++) {
                        FMA2(acc2[1][scx], c, t[dx + scx].u);
                        accw[1][scx] = fmaf(c2, t[dx + scx].f.x, accw[1][scx]);
                    }
                }
            }
            if (dy < 7) {
                #pragma unroll
                for (int dx = 0; dx < 7; dx++) {
                    cc_prev[dx] = cc_cur[dx]; c2_prev[dx] = c2_cur[dx];
                }
            }
        }

        #pragma unroll
        for (int sr = 0; sr < 2; sr++)
            #pragma unroll
            for (int scx = 0; scx < 7; scx++) {
                F2U a; a.u = acc2[sr][scx];
                float den = a.f.x;
                float num = a.f.y + accw[sr][scx];
                y[sr][scx] = __fdividef(num, den);
            }
        __syncthreads();   // all conv reads of svu / coeff smem done

        if (L == 0) {
            // write layer-1 (v,u) directly; refresh coefficients for layer 1
            if (tid < NTAP) {
                float wv = sm_w[(r * 2 + 1) * NTAP + tid];
                float c1 = __expf(a1 * wv);
                scp[2 * tid] = c1; scp[2 * tid + 1] = c1;
                sc2[tid] = c1 * wv;
            }
            #pragma unroll
            for (int sr = 0; sr < 2; sr++)
                #pragma unroll
                for (int scx = 0; scx < 7; scx++) {
                    float yi = y[sr][scx];
                    float vv = __expf(a1 * yi);
                    myvu[(pr0 + sr + PAD) * PW + pc0 + scx + PAD] =
                        make_float2(vv, yi * vv);
                }
        } else {
            // final layer: store y as plain floats overlaid on this image's svu
            float* syf = (float*)myvu;
            #pragma unroll
            for (int sr = 0; sr < 2; sr++)
                #pragma unroll
                for (int scx = 0; scx < 7; scx++)
                    syf[(pr0 + sr) * WW + pc0 + scx] = y[sr][scx];
        }
        __syncthreads();
    }

    // ---- 4x4 avg pool (== two 2x2 pools) -> [7,7] features ----
    if (s < NTAP) {
        const float* syf = (const float*)myvu;
        int qr = s / 7, qc = s % 7;
        float acc = 0.0f;
        #pragma unroll
        for (int dy = 0; dy < 4; dy++)
            #pragma unroll
            for (int dx = 0; dx < 4; dx++)
                acc += syf[(qr * 4 + dy) * WW + qc * 4 + dx];
        g_feat[(b0 + img) * FEAT + r * NTAP + s] = acc * (1.0f / 16.0f);
    }
}

__device__ __forceinline__ float sigf(float z) {
    return 1.0f / (1.0f + __expf(-z));
}

// Fused 3-layer sigmoid MLP. Per-row arithmetic bit-identical to Round 4
// (same g_w*p layout, same fmaf nesting, same i4 order). Restructured for
// latency: 64 blocks x 256 threads (8 warps), 8 batch rows per block.
// Thread = (j = tid&127, row-group = tid>>7 -> 4 rows / 4 accumulator
// chains); weights prefetched one iteration ahead in registers (no staging,
// no intra-layer syncs).
#define MROWS 8
__global__ void __launch_bounds__(256) mlp_kernel(
    const float* __restrict__ b1,
    const float* __restrict__ b2,
    const float* __restrict__ b3,
    float* __restrict__ out)
{
    __shared__ float sf [MROWS][FEAT];
    __shared__ float sh1[MROWS][120];
    __shared__ float sh2[MROWS][84];

    const int tid = threadIdx.x;
    const int b0  = blockIdx.x * MROWS;
    const int j   = tid & 127;           // output-neuron lane
    const int r0  = (tid >> 7) * 4;      // first of 4 batch rows

    // load features: 784 float4 over 256 threads
    {
        const float4* src = (const float4*)(g_feat + b0 * FEAT);
        float4* dst = (float4*)sf;
        #pragma unroll
        for (int i = tid; i < MROWS * FEAT / 4; i += 256) dst[i] = src[i];
    }
    __syncthreads();

    // ---- 392 -> 120 ----
    if (j < 120) {
        float bb = b1[j];
        float acc0 = bb, acc1 = bb, acc2 = bb, acc3 = bb;
        float4 w = g_w1p[j];
        #pragma unroll 7
        for (int i4 = 0; i4 < 98; i4++) {
            float4 wn = (i4 < 97) ? g_w1p[(i4 + 1) * 120 + j] : w;
            float4 s0 = *(const float4*)&sf[r0 + 0][i4 * 4];
            float4 s1 = *(const float4*)&sf[r0 + 1][i4 * 4];
            float4 s2 = *(const float4*)&sf[r0 + 2][i4 * 4];
            float4 s3 = *(const float4*)&sf[r0 + 3][i4 * 4];
            acc0 = fmaf(w.x, s0.x, fmaf(w.y, s0.y, fmaf(w.z, s0.z, fmaf(w.w, s0.w, acc0))));
            acc1 = fmaf(w.x, s1.x, fmaf(w.y, s1.y, fmaf(w.z, s1.z, fmaf(w.w, s1.w, acc1))));
            acc2 = fmaf(w.x, s2.x, fmaf(w.y, s2.y, fmaf(w.z, s2.z, fmaf(w.w, s2.w, acc2))));
            acc3 = fmaf(w.x, s3.x, fmaf(w.y, s3.y, fmaf(w.z, s3.z, fmaf(w.w, s3.w, acc3))));
            w = wn;
        }
        sh1[r0 + 0][j] = sigf(acc0);
        sh1[r0 + 1][j] = sigf(acc1);
        sh1[r0 + 2][j] = sigf(acc2);
        sh1[r0 + 3][j] = sigf(acc3);
    }
    __syncthreads();

    // ---- 120 -> 84 ----
    if (j < 84) {
        float bb = b2[j];
        float acc0 = bb, acc1 = bb, acc2 = bb, acc3 = bb;
        float4 w = g_w2p[j];
        #pragma unroll 6
        for (int i4 = 0; i4 < 30; i4++) {
            float4 wn = (i4 < 29) ? g_w2p[(i4 + 1) * 84 + j] : w;
            float4 s0 = *(const float4*)&sh1[r0 + 0][i4 * 4];
            float4 s1 = *(const float4*)&sh1[r0 + 1][i4 * 4];
            float4 s2 = *(const float4*)&sh1[r0 + 2][i4 * 4];
            float4 s3 = *(const float4*)&sh1[r0 + 3][i4 * 4];
            acc0 = fmaf(w.x, s0.x, fmaf(w.y, s0.y, fmaf(w.z, s0.z, fmaf(w.w, s0.w, acc0))));
            acc1 = fmaf(w.x, s1.x, fmaf(w.y, s1.y, fmaf(w.z, s1.z, fmaf(w.w, s1.w, acc1))));
            acc2 = fmaf(w.x, s2.x, fmaf(w.y, s2.y, fmaf(w.z, s2.z, fmaf(w.w, s2.w, acc2))));
            acc3 = fmaf(w.x, s3.x, fmaf(w.y, s3.y, fmaf(w.z, s3.z, fmaf(w.w, s3.w, acc3))));
            w = wn;
        }
        sh2[r0 + 0][j] = sigf(acc0);
        sh2[r0 + 1][j] = sigf(acc1);
        sh2[r0 + 2][j] = sigf(acc2);
        sh2[r0 + 3][j] = sigf(acc3);
    }
    __syncthreads();

    // ---- 84 -> 10 ----  (80 threads: one (row, j) scalar dot each)
    if (tid < 80) {
        const int jj = tid % 10;
        const int rr = tid / 10;
        float acc = b3[jj];
        #pragma unroll 7
        for (int i4 = 0; i4 < 21; i4++) {
            float4 w = g_w3p[i4 * 10 + jj];
            float4 s = *(const float4*)&sh2[rr][i4 * 4];
            acc = fmaf(w.x, s.x, fmaf(w.y, s.y, fmaf(w.z, s.z, fmaf(w.w, s.w, acc))));
        }
        out[(b0 + rr) * 10 + jj] = sigf(acc);
    }
}

extern "C" void kernel_launch(void* const* d_in, const int* in_sizes, int n_in,
                              void* d_out, int out_size)
{
    const float* x        = (const float*)d_in[0];
    const float* sm_w     = (const float*)d_in[1];
    const float* sm_alpha = (const float*)d_in[2];
    const float* W1       = (const float*)d_in[3];
    const float* b1       = (const float*)d_in[4];
    const float* W2       = (const float*)d_in[5];
    const float* b2       = (const float*)d_in[6];
    const float* W3       = (const float*)d_in[7];
    const float* b3       = (const float*)d_in[8];
    float* out = (float*)d_out;

    const int smem_bytes =
        (IMG_PER_BLK * PW * PW * 2 + 3 * NTAP) * (int)sizeof(float);  // ~39.8KB

    dim3 gridA(BATCH / IMG_PER_BLK, NBR);   // (128, 8)
    smorph_branch_kernel<<<gridA, THREADS_A, smem_bytes>>>(
        x, sm_w, sm_alpha, W1, W2, W3);

    mlp_kernel<<<BATCH / MROWS, 256>>>(b1, b2, b3, out);
}

// round 8
// speedup vs baseline: 1.1205x; 1.0885x over previous
#include <cuda_runtime.h>
#include <cuda_bf16.h>

#define HH 28
#define WW 28
#define PAD 3
#define PW 35           // padded width (odd -> spread smem banks)
#define KK 7
#define NTAP 49
#define BATCH 512
#define NBR 8
#define FEAT 392        // 8 branches * 49

#define IMG_PER_BLK 4
#define STRIPS 56       // (28/7 cols) x (28/2 rows) strips per image
#define THREADS_A (IMG_PER_BLK * STRIPS)   // 224 = 7 full warps

typedef unsigned long long u64;
union F2U { float2 f; u64 u; };

__device__ float g_feat[BATCH * FEAT];
// float4-packed transposed weights: 4 consecutive K-steps per element.
__device__ float4 g_w1p[98 * 120];   // [i4][j]  w = W1[j][4*i4 .. 4*i4+3]
__device__ float4 g_w2p[30 * 84];    // [i4][j]
__device__ float4 g_w3p[21 * 10];    // [i4][j]
#define N_W1P (98 * 120)
#define N_W2P (30 * 84)
#define N_W3P (21 * 10)

#define FMA2(acc, a, b) asm("fma.rn.f32x2 %0, %1, %2, %0;" : "+l"(acc) : "l"(a), "l"(b))

// SMorph factorization:  out = (sum c1*u + sum c2*v) / (sum c1*v)
// v = exp(a*x), u = x*v, c1 = exp(a*w), c2 = w*c1.  Zero SAME-pad <=> (v,u)=(1,0).
// One block = 4 images x 1 branch; each thread owns a 7x2 output strip.
// (Round-4 version, verbatim: measured ~40us, rel_err 7.4e-8.)
__global__ void __launch_bounds__(THREADS_A)
smorph_branch_kernel(const float* __restrict__ x,
                     const float* __restrict__ sm_w,      // [8,2,7,7]
                     const float* __restrict__ sm_alpha,  // [8,2]
                     const float* __restrict__ W1,        // for folded repack
                     const float* __restrict__ W2,
                     const float* __restrict__ W3)
{
    extern __shared__ float smem[];
    float* svu = smem;                              // [4][PW*PW][2]
    float* scp = svu + IMG_PER_BLK * PW * PW * 2;   // [49] float2 (c1,c1)
    float* sc2 = scp + 2 * NTAP;                    // [49]

    const int tid = threadIdx.x;
    const int b0  = blockIdx.x * IMG_PER_BLK;
    const int r   = blockIdx.y;

    // ---- folded one-shot weight repack (float4 of 4 consecutive K-steps) ----
    {
        int gid = blockIdx.y * gridDim.x + blockIdx.x;
        int t = gid * THREADS_A + tid;
        if (t < N_W1P) {
            int i4 = t / 120, j = t % 120;
            g_w1p[t] = *(const float4*)(W1 + j * FEAT + 4 * i4);
        } else if (t < N_W1P + N_W2P) {
            int q = t - N_W1P; int i4 = q / 84, j = q % 84;
            g_w2p[q] = *(const float4*)(W2 + j * 120 + 4 * i4);
        } else if (t < N_W1P + N_W2P + N_W3P) {
            int q = t - N_W1P - N_W2P; int i4 = q / 10, j = q % 10;
            g_w3p[q] = *(const float4*)(W3 + j * 84 + 4 * i4);
        }
    }

    const int img = tid / STRIPS;
    const int s   = tid % STRIPS;
    const int pr0 = (s / 4) * 2;   // strip top row   (0..26)
    const int pc0 = (s % 4) * 7;   // strip left col  (0,7,14,21)

    float2* myvu = (float2*)svu + img * (PW * PW);
    const float* xim = x + (b0 + img) * (HH * WW);

    const float a0 = sm_alpha[r * 2 + 0];
    const float a1 = sm_alpha[r * 2 + 1];

    // init to halo (v,u)=(1,0); interior overwritten below
    {
        float2* p = (float2*)svu;
        for (int i = tid; i < IMG_PER_BLK * PW * PW; i += THREADS_A)
            p[i] = make_float2(1.0f, 0.0f);
    }
    // layer-0 coefficients
    if (tid < NTAP) {
        float wv = sm_w[(r * 2 + 0) * NTAP + tid];
        float c1 = __expf(a0 * wv);
        scp[2 * tid] = c1; scp[2 * tid + 1] = c1;
        sc2[tid] = c1 * wv;
    }
    __syncthreads();

    // layer-0 interior fill
    for (int i = s; i < HH * WW; i += STRIPS) {
        float xi = xim[i];
        float vv = __expf(a0 * xi);
        int pr = i / WW, pc = i % WW;
        myvu[(pr + PAD) * PW + pc + PAD] = make_float2(vv, xi * vv);
    }
    __syncthreads();

    float y[2][7];

    #pragma unroll 1
    for (int L = 0; L < 2; L++) {
        // ---- conv: 7x2 strip, 8 input rows, coefficient rows cached in regs ----
        u64   acc2[2][7];    // packed (den = sum c1*v, num_u = sum c1*u)
        float accw[2][7];    // sum c2*v
        #pragma unroll
        for (int i = 0; i < 2; i++)
            #pragma unroll
            for (int j = 0; j < 7; j++) { acc2[i][j] = 0ull; accw[i][j] = 0.0f; }

        F2U cc_cur[7], cc_prev[7];
        float c2_cur[7], c2_prev[7];

        #pragma unroll
        for (int dy = 0; dy < 8; dy++) {
            F2U t[13];
            const float2* rowp = myvu + (pr0 + dy) * PW + pc0;
            #pragma unroll
            for (int k = 0; k < 13; k++) t[k].f = rowp[k];

            if (dy < 7) {
                #pragma unroll
                for (int dx = 0; dx < 7; dx++) {
                    cc_cur[dx].f = ((const float2*)scp)[dy * 7 + dx];
                    c2_cur[dx]   = sc2[dy * 7 + dx];
                }
                // sr = 0 uses tap row ky = dy
                #pragma unroll
                for (int dx = 0; dx < 7; dx++) {
                    u64 c = cc_cur[dx].u; float c2 = c2_cur[dx];
                    #pragma unroll
                    for (int scx = 0; scx < 7; scx++) {
                        FMA2(acc2[0][scx], c, t[dx + scx].u);
                        accw[0][scx] = fmaf(c2, t[dx + scx].f.x, accw[0][scx]);
                    }
                }
            }
            if (dy >= 1) {
                // sr = 1 uses tap row ky = dy-1 (cached from previous iteration)
                #pragma unroll
                for (int dx = 0; dx < 7; dx++) {
                    u64 c = cc_prev[dx].u; float c2 = c2_prev[dx];
                    #pragma unroll
                    for (int scx = 0; scx < 7; scx++) {
                        FMA2(acc2[1][scx], c, t[dx + scx].u);
                        accw[1][scx] = fmaf(c2, t[dx + scx].f.x, accw[1][scx]);
                    }
                }
            }
            if (dy < 7) {
                #pragma unroll
                for (int dx = 0; dx < 7; dx++) {
                    cc_prev[dx] = cc_cur[dx]; c2_prev[dx] = c2_cur[dx];
                }
            }
        }

        #pragma unroll
        for (int sr = 0; sr < 2; sr++)
            #pragma unroll
            for (int scx = 0; scx < 7; scx++) {
                F2U a; a.u = acc2[sr][scx];
                float den = a.f.x;
                float num = a.f.y + accw[sr][scx];
                y[sr][scx] = __fdividef(num, den);
            }
        __syncthreads();   // all conv reads of svu / coeff smem done

        if (L == 0) {
            // write layer-1 (v,u) directly; refresh coefficients for layer 1
            if (tid < NTAP) {
                float wv = sm_w[(r * 2 + 1) * NTAP + tid];
                float c1 = __expf(a1 * wv);
                scp[2 * tid] = c1; scp[2 * tid + 1] = c1;
                sc2[tid] = c1 * wv;
            }
            #pragma unroll
            for (int sr = 0; sr < 2; sr++)
                #pragma unroll
                for (int scx = 0; scx < 7; scx++) {
                    float yi = y[sr][scx];
                    float vv = __expf(a1 * yi);
                    myvu[(pr0 + sr + PAD) * PW + pc0 + scx + PAD] =
                        make_float2(vv, yi * vv);
                }
        } else {
            // final layer: store y as plain floats overlaid on this image's svu
            float* syf = (float*)myvu;
            #pragma unroll
            for (int sr = 0; sr < 2; sr++)
                #pragma unroll
                for (int scx = 0; scx < 7; scx++)
                    syf[(pr0 + sr) * WW + pc0 + scx] = y[sr][scx];
        }
        __syncthreads();
    }

    // ---- 4x4 avg pool (== two 2x2 pools) -> [7,7] features ----
    if (s < NTAP) {
        const float* syf = (const float*)myvu;
        int qr = s / 7, qc = s % 7;
        float acc = 0.0f;
        #pragma unroll
        for (int dy = 0; dy < 4; dy++)
            #pragma unroll
            for (int dx = 0; dx < 4; dx++)
                acc += syf[(qr * 4 + dy) * WW + qc * 4 + dx];
        g_feat[(b0 + img) * FEAT + r * NTAP + s] = acc * (1.0f / 16.0f);
    }
}

__device__ __forceinline__ float sigf(float z) {
    return 1.0f / (1.0f + __expf(-z));
}

// Dot-product group: 4 consecutive i4 weight loads issued before any
// consuming FMA (prefetch depth 4), two batch rows per thread.
// Per-row fmaf nesting/order identical to Round 4.
#define MLP_GROUP4(GW, SA, SB, I4, STRIDE)                                         \
    {                                                                              \
        float4 w0 = GW[(I4 + 0) * STRIDE + j];                                     \
        float4 w1 = GW[(I4 + 1) * STRIDE + j];                                     \
        float4 w2 = GW[(I4 + 2) * STRIDE + j];                                     \
        float4 w3 = GW[(I4 + 3) * STRIDE + j];                                     \
        float4 sa0 = *(const float4*)&SA[(I4 + 0) * 4];                            \
        float4 sb0 = *(const float4*)&SB[(I4 + 0) * 4];                            \
        float4 sa1 = *(const float4*)&SA[(I4 + 1) * 4];                            \
        float4 sb1 = *(const float4*)&SB[(I4 + 1) * 4];                            \
        float4 sa2 = *(const float4*)&SA[(I4 + 2) * 4];                            \
        float4 sb2 = *(const float4*)&SB[(I4 + 2) * 4];                            \
        float4 sa3 = *(const float4*)&SA[(I4 + 3) * 4];                            \
        float4 sb3 = *(const float4*)&SB[(I4 + 3) * 4];                            \
        accA = fmaf(w0.x, sa0.x, fmaf(w0.y, sa0.y, fmaf(w0.z, sa0.z, fmaf(w0.w, sa0.w, accA)))); \
        accB = fmaf(w0.x, sb0.x, fmaf(w0.y, sb0.y, fmaf(w0.z, sb0.z, fmaf(w0.w, sb0.w, accB)))); \
        accA = fmaf(w1.x, sa1.x, fmaf(w1.y, sa1.y, fmaf(w1.z, sa1.z, fmaf(w1.w, sa1.w, accA)))); \
        accB = fmaf(w1.x, sb1.x, fmaf(w1.y, sb1.y, fmaf(w1.z, sb1.z, fmaf(w1.w, sb1.w, accB)))); \
        accA = fmaf(w2.x, sa2.x, fmaf(w2.y, sa2.y, fmaf(w2.z, sa2.z, fmaf(w2.w, sa2.w, accA)))); \
        accB = fmaf(w2.x, sb2.x, fmaf(w2.y, sb2.y, fmaf(w2.z, sb2.z, fmaf(w2.w, sb2.w, accB)))); \
        accA = fmaf(w3.x, sa3.x, fmaf(w3.y, sa3.y, fmaf(w3.z, sa3.z, fmaf(w3.w, sa3.w, accA)))); \
        accB = fmaf(w3.x, sb3.x, fmaf(w3.y, sb3.y, fmaf(w3.z, sb3.z, fmaf(w3.w, sb3.w, accB)))); \
    }

// Fused 3-layer sigmoid MLP. 128 blocks x 256 threads:
// j = tid&127 (output lane), row-group = tid>>7 (2 batch rows each).
// Prefetch depth 4; per-row arithmetic bit-identical to Round 4.
#define MROWS 4
__global__ void __launch_bounds__(256) mlp_kernel(
    const float* __restrict__ b1,
    const float* __restrict__ b2,
    const float* __restrict__ b3,
    float* __restrict__ out)
{
    __shared__ float sf [MROWS][FEAT];
    __shared__ float sh1[MROWS][120];
    __shared__ float sh2[MROWS][84];

    const int tid = threadIdx.x;
    const int b0  = blockIdx.x * MROWS;
    const int j   = tid & 127;           // output-neuron lane
    const int rA  = (tid >> 7) * 2;      // rows rA, rA+1
    const int rB  = rA + 1;

    {
        const float4* src = (const float4*)(g_feat + b0 * FEAT);
        float4* dst = (float4*)sf;
        #pragma unroll
        for (int i = tid; i < MROWS * FEAT / 4; i += 256) dst[i] = src[i];
    }
    __syncthreads();

    // ---- 392 -> 120 : 98 i4-groups = 24x4 + 2 ----
    if (j < 120) {
        float bb = b1[j];
        float accA = bb, accB = bb;
        const float* SA = &sf[rA][0];
        const float* SB = &sf[rB][0];
        #pragma unroll 3
        for (int g = 0; g < 24; g++)
            MLP_GROUP4(g_w1p, SA, SB, g * 4, 120)
        #pragma unroll
        for (int i4 = 96; i4 < 98; i4++) {
            float4 w  = g_w1p[i4 * 120 + j];
            float4 sa = *(const float4*)&SA[i4 * 4];
            float4 sb = *(const float4*)&SB[i4 * 4];
            accA = fmaf(w.x, sa.x, fmaf(w.y, sa.y, fmaf(w.z, sa.z, fmaf(w.w, sa.w, accA))));
            accB = fmaf(w.x, sb.x, fmaf(w.y, sb.y, fmaf(w.z, sb.z, fmaf(w.w, sb.w, accB))));
        }
        sh1[rA][j] = sigf(accA);
        sh1[rB][j] = sigf(accB);
    }
    __syncthreads();

    // ---- 120 -> 84 : 30 i4-groups = 7x4 + 2 ----
    if (j < 84) {
        float bb = b2[j];
        float accA = bb, accB = bb;
        const float* SA = &sh1[rA][0];
        const float* SB = &sh1[rB][0];
        #pragma unroll 7
        for (int g = 0; g < 7; g++)
            MLP_GROUP4(g_w2p, SA, SB, g * 4, 84)
        #pragma unroll
        for (int i4 = 28; i4 < 30; i4++) {
            float4 w  = g_w2p[i4 * 84 + j];
            float4 sa = *(const float4*)&SA[i4 * 4];
            float4 sb = *(const float4*)&SB[i4 * 4];
            accA = fmaf(w.x, sa.x, fmaf(w.y, sa.y, fmaf(w.z, sa.z, fmaf(w.w, sa.w, accA))));
            accB = fmaf(w.x, sb.x, fmaf(w.y, sb.y, fmaf(w.z, sb.z, fmaf(w.w, sb.w, accB))));
        }
        sh2[rA][j] = sigf(accA);
        sh2[rB][j] = sigf(accB);
    }
    __syncthreads();

    // ---- 84 -> 10 ----  (40 threads: one (row, j) scalar dot each)
    if (tid < 40) {
        const int jj = tid % 10;
        const int rr = tid / 10;
        float acc = b3[jj];
        #pragma unroll 7
        for (int i4 = 0; i4 < 21; i4++) {
            float4 w = g_w3p[i4 * 10 + jj];
            float4 s = *(const float4*)&sh2[rr][i4 * 4];
            acc = fmaf(w.x, s.x, fmaf(w.y, s.y, fmaf(w.z, s.z, fmaf(w.w, s.w, acc))));
        }
        out[(b0 + rr) * 10 + jj] = sigf(acc);
    }
}

extern "C" void kernel_launch(void* const* d_in, const int* in_sizes, int n_in,
                              void* d_out, int out_size)
{
    const float* x        = (const float*)d_in[0];
    const float* sm_w     = (const float*)d_in[1];
    const float* sm_alpha = (const float*)d_in[2];
    const float* W1       = (const float*)d_in[3];
    const float* b1       = (const float*)d_in[4];
    const float* W2       = (const float*)d_in[5];
    const float* b2       = (const float*)d_in[6];
    const float* W3       = (const float*)d_in[7];
    const float* b3       = (const float*)d_in[8];
    float* out = (float*)d_out;

    const int smem_bytes =
        (IMG_PER_BLK * PW * PW * 2 + 3 * NTAP) * (int)sizeof(float);  // ~39.8KB

    dim3 gridA(BATCH / IMG_PER_BLK, NBR);   // (128, 8)
    smorph_branch_kernel<<<gridA, THREADS_A, smem_bytes>>>(
        x, sm_w, sm_alpha, W1, W2, W3);

    mlp_kernel<<<BATCH / MROWS, 256>>>(b1, b2, b3, out);
}